// round 12
// baseline (speedup 1.0000x reference)
#include <cuda_runtime.h>
#include <cuda_bf16.h>
#include <cuda_fp16.h>
#include <math.h>
#include <stdint.h>

#define NEG_SLOPE 0.2f
#define EPS_BN 1e-5f
#define N_NODES 20000
#define F_IN_D 128
#define E_EDGES 320000
#define E_TOT (E_EDGES + N_NODES)
#define HD_MAX 256
#define G_GRAPHS 64
#define OUT_DIM 128
#define NCLS_D 10

// ---------------- scratch ----------------
__device__ __half g_h[N_NODES * HD_MAX];          // GEMM output, fp16 (gather source)
__device__ float g_o[N_NODES * HD_MAX];           // agg output (pre-BN), fp32
__device__ float g_es[N_NODES * 4];               // per-(node, column-block) partials
__device__ float g_ed[N_NODES * 4];
__device__ int   g_deg[N_NODES];
__device__ int   g_rowptr[N_NODES + 1];
__device__ int   g_cursor[N_NODES];
__device__ int   g_csrc[E_TOT];
__device__ float g_bnstat[3 * 2 * HD_MAX];
__device__ float g_feat[G_GRAPHS * OUT_DIM];
__device__ int   g_start[G_GRAPHS + 1];

// ---------------- utility ----------------
__global__ void k_zero_i(int* p, int n) {
    int i = blockIdx.x * blockDim.x + threadIdx.x;
    if (i < n) p[i] = 0;
}

// ---------------- CSR build ----------------
__global__ void k_deg(const int* __restrict__ ei, int E, int ET, int* __restrict__ deg) {
    int e = blockIdx.x * blockDim.x + threadIdx.x;
    if (e >= ET) return;
    int d = (e < E) ? ei[E + e] : (e - E);
    atomicAdd(&deg[d], 1);
}

__global__ void k_scan(const int* __restrict__ deg, int* __restrict__ rowptr,
                       int* __restrict__ cursor, int n) {
    __shared__ int sh[1024];
    int t = threadIdx.x;
    int items = (n + 1023) / 1024;
    int b0 = t * items;
    int loc = 0;
    for (int i = 0; i < items; i++) {
        int idx = b0 + i;
        if (idx < n) loc += deg[idx];
    }
    sh[t] = loc;
    __syncthreads();
    for (int off = 1; off < 1024; off <<= 1) {
        int v = (t >= off) ? sh[t - off] : 0;
        __syncthreads();
        sh[t] += v;
        __syncthreads();
    }
    int run = sh[t] - loc;
    for (int i = 0; i < items; i++) {
        int idx = b0 + i;
        if (idx < n) {
            rowptr[idx] = run;
            cursor[idx] = run;
            run += deg[idx];
        }
    }
    if (t == 1023) rowptr[n] = sh[1023];
}

__global__ void k_fill(const int* __restrict__ ei, int E, int ET,
                       int* __restrict__ cursor, int* __restrict__ csrc) {
    int e = blockIdx.x * blockDim.x + threadIdx.x;
    if (e >= ET) return;
    int s, d;
    if (e < E) { s = ei[e]; d = ei[E + e]; }
    else { s = e - E; d = e - E; }
    int pos = atomicAdd(&cursor[d], 1);
    csrc[pos] = s;
}

// graph ranges (batch sorted); also zero feat + bn stat accumulators
__global__ void k_ranges(const int* __restrict__ batch, int n, int* __restrict__ start,
                         float* __restrict__ feat, float* __restrict__ stat) {
    int g = threadIdx.x;
    for (int i = g; i < G_GRAPHS * OUT_DIM; i += 128) feat[i] = 0.f;
    for (int i = g; i < 3 * 2 * HD_MAX; i += 128) stat[i] = 0.f;
    if (g > G_GRAPHS) return;
    if (g == G_GRAPHS) { start[G_GRAPHS] = n; return; }
    int lo = 0, hi = n;
    while (lo < hi) {
        int mid = (lo + hi) >> 1;
        if (batch[mid] < g) lo = mid + 1; else hi = mid;
    }
    start[g] = lo;
}

// ---------------- bf16 split helpers (GEMM inputs) ----------------
__device__ __forceinline__ uint32_t pack_hi(float x0, float x1) {
    __nv_bfloat16 h0 = __float2bfloat16_rn(x0);
    __nv_bfloat16 h1 = __float2bfloat16_rn(x1);
    return (uint32_t)__bfloat16_as_ushort(h0) | ((uint32_t)__bfloat16_as_ushort(h1) << 16);
}
__device__ __forceinline__ uint32_t pack_lo(float x0, float x1) {
    __nv_bfloat16 h0 = __float2bfloat16_rn(x0);
    __nv_bfloat16 h1 = __float2bfloat16_rn(x1);
    __nv_bfloat16 l0 = __float2bfloat16_rn(x0 - __bfloat162float(h0));
    __nv_bfloat16 l1 = __float2bfloat16_rn(x1 - __bfloat162float(h1));
    return (uint32_t)__bfloat16_as_ushort(l0) | ((uint32_t)__bfloat16_as_ushort(l1) << 16);
}
// fp16 pack (h storage)
__device__ __forceinline__ uint32_t pack_h16(float x0, float x1) {
    __half2 h = __floats2half2_rn(x0, x1);
    return *(uint32_t*)&h;
}
__device__ __forceinline__ void mma_bf16(float* c, const uint32_t* a, uint32_t b0, uint32_t b1) {
    asm volatile(
        "mma.sync.aligned.m16n8k16.row.col.f32.bf16.bf16.f32 "
        "{%0,%1,%2,%3}, {%4,%5,%6,%7}, {%8,%9}, {%0,%1,%2,%3};"
        : "+f"(c[0]), "+f"(c[1]), "+f"(c[2]), "+f"(c[3])
        : "r"(a[0]), "r"(a[1]), "r"(a[2]), "r"(a[3]), "r"(b0), "r"(b1));
}

// ---------------- Tensor-core GEMM: 128x64 tiles, fp16 output --------------------
#define APAD 136
#define BPAD 72
template <bool FUSE>
__global__ __launch_bounds__(256, 3) void k_gemm_tc(const float* __restrict__ A,
                                                    const float* __restrict__ B,
                                                    __half* __restrict__ C,
                                                    int M, int K, int Nd, int nNodes,
                                                    const float* __restrict__ bnsum,
                                                    const float* __restrict__ bnsq,
                                                    const float* __restrict__ gamma,
                                                    const float* __restrict__ beta,
                                                    const float* __restrict__ asrc,
                                                    const float* __restrict__ adst,
                                                    float* __restrict__ es,
                                                    float* __restrict__ ed) {
    __shared__ __align__(16) uint32_t Ah[2][8][APAD];
    __shared__ __align__(16) uint32_t Al[2][8][APAD];
    __shared__ __align__(16) uint32_t Bh[2][8][BPAD];
    __shared__ __align__(16) uint32_t Bl[2][8][BPAD];
    __shared__ float ssc[HD_MAX], ssh[HD_MAX];
    __shared__ float sAs[64], sAd[64];
    __shared__ float sE[128][2][2];
    int t = threadIdx.x;
    int bm = blockIdx.x * 128, bn = blockIdx.y * 64;

    if (t < 64) { sAs[t] = asrc[bn + t]; sAd[t] = adst[bn + t]; }
    if (FUSE && t < K) {
        float mu = bnsum[t] / (float)nNodes;
        float var = bnsq[t] / (float)nNodes - mu * mu;
        float sc = gamma[t] * rsqrtf(var + EPS_BN);
        ssc[t] = sc;
        ssh[t] = beta[t] - mu * sc;
    }
    __syncthreads();

    int warp = t >> 5, lane = t & 31;
    int wm = (warp >> 1) * 32, wcol = warp & 1, wn = wcol * 32;
    int gid = lane >> 2, tig = lane & 3;

    int ar = t >> 1, akb = (t & 1) * 8;
    bool avalid = (bm + ar) < M;
    const float* Ap = A + (size_t)(bm + ar) * K + akb;
    const float* Bp = B + (size_t)(warp * 2) * Nd + bn + lane * 2;

    float acc[2][4][4];
#pragma unroll
    for (int mt = 0; mt < 2; mt++)
#pragma unroll
        for (int nt = 0; nt < 4; nt++)
#pragma unroll
            for (int c = 0; c < 4; c++) acc[mt][nt][c] = 0.f;

    float4 a0, a1;
    float2 b0, b1;

    auto stage = [&](int buf, int k0) {
        float v[8] = {a0.x, a0.y, a0.z, a0.w, a1.x, a1.y, a1.z, a1.w};
        if (FUSE) {
#pragma unroll
            for (int j = 0; j < 8; j++)
                v[j] = fmaxf(v[j] * ssc[k0 + akb + j] + ssh[k0 + akb + j], 0.f);
        }
#pragma unroll
        for (int j2 = 0; j2 < 4; j2++) {
            Ah[buf][(akb >> 1) + j2][ar] = pack_hi(v[2 * j2], v[2 * j2 + 1]);
            Al[buf][(akb >> 1) + j2][ar] = pack_lo(v[2 * j2], v[2 * j2 + 1]);
        }
        Bh[buf][warp][lane * 2]     = pack_hi(b0.x, b1.x);
        Bh[buf][warp][lane * 2 + 1] = pack_hi(b0.y, b1.y);
        Bl[buf][warp][lane * 2]     = pack_lo(b0.x, b1.x);
        Bl[buf][warp][lane * 2 + 1] = pack_lo(b0.y, b1.y);
    };

    if (avalid) { a0 = *(const float4*)Ap; a1 = *(const float4*)(Ap + 4); }
    else { a0 = make_float4(0, 0, 0, 0); a1 = a0; }
    b0 = *(const float2*)Bp;
    b1 = *(const float2*)(Bp + Nd);
    stage(0, 0);
    __syncthreads();

    int nk = K >> 4;
    for (int kt = 0; kt < nk; kt++) {
        int buf = kt & 1;
        if (kt + 1 < nk) {
            int k0 = (kt + 1) << 4;
            if (avalid) { a0 = *(const float4*)(Ap + k0); a1 = *(const float4*)(Ap + k0 + 4); }
            else { a0 = make_float4(0, 0, 0, 0); a1 = a0; }
            b0 = *(const float2*)(Bp + (size_t)k0 * Nd);
            b1 = *(const float2*)(Bp + (size_t)(k0 + 1) * Nd);
        }

        uint32_t fbh[4][2], fbl[4][2];
#pragma unroll
        for (int nt = 0; nt < 4; nt++) {
            int c0 = wn + nt * 8 + gid;
            fbh[nt][0] = Bh[buf][tig][c0];
            fbh[nt][1] = Bh[buf][tig + 4][c0];
            fbl[nt][0] = Bl[buf][tig][c0];
            fbl[nt][1] = Bl[buf][tig + 4][c0];
        }
#pragma unroll
        for (int mt = 0; mt < 2; mt++) {
            int r0i = wm + mt * 16 + gid;
            uint32_t ah[4], al[4];
            ah[0] = Ah[buf][tig][r0i];
            ah[1] = Ah[buf][tig][r0i + 8];
            ah[2] = Ah[buf][tig + 4][r0i];
            ah[3] = Ah[buf][tig + 4][r0i + 8];
            al[0] = Al[buf][tig][r0i];
            al[1] = Al[buf][tig][r0i + 8];
            al[2] = Al[buf][tig + 4][r0i];
            al[3] = Al[buf][tig + 4][r0i + 8];
#pragma unroll
            for (int nt = 0; nt < 4; nt++)
                mma_bf16(acc[mt][nt], ah, fbh[nt][0], fbh[nt][1]);
#pragma unroll
            for (int nt = 0; nt < 4; nt++)
                mma_bf16(acc[mt][nt], ah, fbl[nt][0], fbl[nt][1]);
#pragma unroll
            for (int nt = 0; nt < 4; nt++)
                mma_bf16(acc[mt][nt], al, fbh[nt][0], fbh[nt][1]);
        }

        if (kt + 1 < nk) {
            int k0 = (kt + 1) << 4;
            stage(buf ^ 1, k0);
        }
        __syncthreads();
    }

    // ---- epilogue: store C (fp16) + attention-score partials ----
    uint32_t* Cb = (uint32_t*)C;
#pragma unroll
    for (int mt = 0; mt < 2; mt++) {
        int r0i = bm + wm + mt * 16 + gid;
        int r1i = r0i + 8;
#pragma unroll
        for (int nt = 0; nt < 4; nt++) {
            int cc = bn + wn + nt * 8 + tig * 2;
            if (r0i < M) Cb[((size_t)r0i * Nd + cc) >> 1] =
                pack_h16(acc[mt][nt][0], acc[mt][nt][1]);
            if (r1i < M) Cb[((size_t)r1i * Nd + cc) >> 1] =
                pack_h16(acc[mt][nt][2], acc[mt][nt][3]);
        }
#pragma unroll
        for (int half = 0; half < 2; half++) {
            float pes = 0.f, ped = 0.f;
#pragma unroll
            for (int nt = 0; nt < 4; nt++) {
#pragma unroll
                for (int j = 0; j < 2; j++) {
                    int cl = wn + nt * 8 + tig * 2 + j;
                    float v = acc[mt][nt][half * 2 + j];
                    pes += v * sAs[cl];
                    ped += v * sAd[cl];
                }
            }
            pes += __shfl_xor_sync(0xffffffffu, pes, 1);
            pes += __shfl_xor_sync(0xffffffffu, pes, 2);
            ped += __shfl_xor_sync(0xffffffffu, ped, 1);
            ped += __shfl_xor_sync(0xffffffffu, ped, 2);
            if (tig == 0) {
                int r = wm + mt * 16 + gid + half * 8;
                sE[r][wcol][0] = pes;
                sE[r][wcol][1] = ped;
            }
        }
    }
    __syncthreads();
    if (t < 128) {
        int row = bm + t;
        if (row < M) {
            es[row * 4 + blockIdx.y] = sE[t][0][0] + sE[t][1][0];
            ed[row * 4 + blockIdx.y] = sE[t][0][1] + sE[t][1][1];
        }
    }
}

// ---------------- single-pass softmax + aggregation (fp16 gather) + BN stats --------
template <int H, int D>
__global__ __launch_bounds__(256) void k_agg_fused(
        const __half* __restrict__ h, const float* __restrict__ es,
        const float* __restrict__ ed, const int* __restrict__ rowptr,
        const int* __restrict__ csrc, const float* __restrict__ bias,
        float* __restrict__ outp, float* __restrict__ bnsum,
        float* __restrict__ bnsq, int n) {
    constexpr int HD = H * D, PL = HD / 32, NV = PL / 4;
    __shared__ float sm8[8][HD];
    int t = threadIdx.x;
    int node = (blockIdx.x * 256 + t) >> 5;
    int lane = t & 31;
    int warp = t >> 5;
    const int hme = (lane * PL) / D;

    float4 res[NV];
#pragma unroll
    for (int q = 0; q < NV; q++) res[q] = make_float4(0.f, 0.f, 0.f, 0.f);

    if (node < n) {
        float edme;
        if (H == 1) edme = ed[node * 4] + ed[node * 4 + 1];
        else        edme = ed[node * 4 + hme];
        int p0 = rowptr[node], p1 = rowptr[node + 1];
        float4 acc[NV];
#pragma unroll
        for (int q = 0; q < NV; q++) acc[q] = make_float4(0.f, 0.f, 0.f, 0.f);
        float z = 0.f;
#pragma unroll 2
        for (int p = p0; p < p1; p++) {
            int s = csrc[p];
            float e;
            if (H == 1) {
                float2 e2 = *(const float2*)&es[s * 4];
                e = e2.x + e2.y + edme;
            } else {
                e = es[s * 4 + hme] + edme;
            }
            e = (e > 0.f) ? e : NEG_SLOPE * e;
            float w = __expf(e);
            z += w;
            const __half* hs = h + (size_t)s * HD + lane * PL;
            uint32_t u[PL / 2];
            if (PL == 8) *(uint4*)u = *(const uint4*)hs;
            else         *(uint2*)u = *(const uint2*)hs;
#pragma unroll
            for (int q = 0; q < NV; q++) {
                float2 f0 = __half22float2(*(__half2*)&u[q * 2]);
                float2 f1 = __half22float2(*(__half2*)&u[q * 2 + 1]);
                acc[q].x += f0.x * w; acc[q].y += f0.y * w;
                acc[q].z += f1.x * w; acc[q].w += f1.y * w;
            }
        }
        float iz = 1.f / z;
        const float4* bb = (const float4*)(bias + lane * PL);
        float4* op = (float4*)(outp + (size_t)node * HD + lane * PL);
#pragma unroll
        for (int q = 0; q < NV; q++) {
            float4 b = bb[q];
            res[q] = make_float4(acc[q].x * iz + b.x, acc[q].y * iz + b.y,
                                 acc[q].z * iz + b.z, acc[q].w * iz + b.w);
            op[q] = res[q];
        }
    }

    // BN stats: stage rows in smem, channel-wise reduce, 2 global atomics/ch/block
#pragma unroll
    for (int q = 0; q < NV; q++)
        *(float4*)&sm8[warp][lane * PL + q * 4] = res[q];
    __syncthreads();
    if (t < HD) {
        float s = 0.f, q2 = 0.f;
#pragma unroll
        for (int w = 0; w < 8; w++) {
            float v = sm8[w][t];
            s += v;
            q2 += v * v;
        }
        atomicAdd(&bnsum[t], s);
        atomicAdd(&bnsq[t], q2);
    }
}

// ---------------- pooling (BN scale/shift computed in-block from stats) -------------
__global__ void k_pool(const float* __restrict__ o, const int* __restrict__ start,
                       const float* __restrict__ bnsum, const float* __restrict__ bnsq,
                       const float* __restrict__ gamma, const float* __restrict__ beta,
                       int n, float* __restrict__ feat) {
    __shared__ float sm[4][OUT_DIM];
    __shared__ float ssc[OUT_DIM], ssh[OUT_DIM];
    int c = threadIdx.x & 127;
    int rgrp = threadIdx.x >> 7;
    if (threadIdx.x < OUT_DIM) {
        float mu = bnsum[c] / (float)n;
        float var = bnsq[c] / (float)n - mu * mu;
        float sc2 = gamma[c] * rsqrtf(var + EPS_BN);
        ssc[c] = sc2;
        ssh[c] = beta[c] - mu * sc2;
    }
    __syncthreads();
    int g = blockIdx.x;
    int part = blockIdx.y;
    int s0 = start[g], s1 = start[g + 1];
    int len = s1 - s0;
    int chunk = (len + 3) >> 2;
    int r0 = s0 + part * chunk;
    int r1 = min(s1, r0 + chunk);
    float sc = ssc[c], sh = ssh[c];
    float sum = 0.f;
    for (int r = r0 + rgrp; r < r1; r += 4) {
        float v = o[(size_t)r * OUT_DIM + c];
        sum += fmaxf(v * sc + sh, 0.f);
    }
    sm[rgrp][c] = sum;
    __syncthreads();
    if (threadIdx.x < OUT_DIM) {
        float s = sm[0][c] + sm[1][c] + sm[2][c] + sm[3][c];
        atomicAdd(&feat[g * OUT_DIM + c], s);
    }
}

// ---------------- heads ----------------
__global__ void k_heads(const float* __restrict__ featsum, const int* __restrict__ start,
                        const float* __restrict__ clfW, const float* __restrict__ clfb,
                        const float* __restrict__ dW1, const float* __restrict__ db1,
                        const float* __restrict__ dW2, const float* __restrict__ db2,
                        float* __restrict__ out) {
    __shared__ float f[OUT_DIM];
    __shared__ float dh[64];
    int g = blockIdx.x, t = threadIdx.x;
    float c = (float)max(start[g + 1] - start[g], 1);
    f[t] = featsum[g * OUT_DIM + t] / c;
    out[G_GRAPHS * NCLS_D + G_GRAPHS * 2 + g * OUT_DIM + t] = f[t];
    __syncthreads();
    if (t < 64) {
        float s = db1[t];
        for (int k = 0; k < OUT_DIM; k++) s += f[k] * dW1[k * 64 + t];
        dh[t] = fmaxf(s, 0.f);
    }
    if (t < NCLS_D) {
        float s = clfb[t];
        for (int k = 0; k < OUT_DIM; k++) s += f[k] * clfW[k * NCLS_D + t];
        out[g * NCLS_D + t] = s;
    }
    __syncthreads();
    if (t < 2) {
        float s = db2[t];
        for (int k = 0; k < 64; k++) s += dh[k] * dW2[k * 2 + t];
        out[G_GRAPHS * NCLS_D + g * 2 + t] = s;
    }
}

// ---------------- launch ----------------
static inline int cdiv(int a, int b) { return (a + b - 1) / b; }

extern "C" void kernel_launch(void* const* d_in, const int* in_sizes, int n_in,
                              void* d_out, int out_size) {
    const float* x = (const float*)d_in[0];
    const int* ei = (const int*)d_in[1];
    const int* batch = (const int*)d_in[2];
    const float* W[3]   = {(const float*)d_in[3],  (const float*)d_in[9],  (const float*)d_in[15]};
    const float* Asr[3] = {(const float*)d_in[4],  (const float*)d_in[10], (const float*)d_in[16]};
    const float* Ads[3] = {(const float*)d_in[5],  (const float*)d_in[11], (const float*)d_in[17]};
    const float* Bi[3]  = {(const float*)d_in[6],  (const float*)d_in[12], (const float*)d_in[18]};
    const float* Ga[3]  = {(const float*)d_in[7],  (const float*)d_in[13], (const float*)d_in[19]};
    const float* Be[3]  = {(const float*)d_in[8],  (const float*)d_in[14], (const float*)d_in[20]};
    const float* clfW = (const float*)d_in[21];
    const float* clfb = (const float*)d_in[22];
    const float* dW1 = (const float*)d_in[23];
    const float* db1 = (const float*)d_in[24];
    const float* dW2 = (const float*)d_in[25];
    const float* db2 = (const float*)d_in[26];

    int N = in_sizes[0] / F_IN_D;
    int E = in_sizes[1] / 2;
    int ET = E + N;

    float *p_o, *p_es, *p_ed, *p_stat, *p_feat;
    __half* p_h;
    int *p_deg, *p_rowptr, *p_cursor, *p_csrc, *p_start;
    cudaGetSymbolAddress((void**)&p_h, g_h);
    cudaGetSymbolAddress((void**)&p_o, g_o);
    cudaGetSymbolAddress((void**)&p_es, g_es);
    cudaGetSymbolAddress((void**)&p_ed, g_ed);
    cudaGetSymbolAddress((void**)&p_deg, g_deg);
    cudaGetSymbolAddress((void**)&p_rowptr, g_rowptr);
    cudaGetSymbolAddress((void**)&p_cursor, g_cursor);
    cudaGetSymbolAddress((void**)&p_csrc, g_csrc);
    cudaGetSymbolAddress((void**)&p_stat, g_bnstat);
    cudaGetSymbolAddress((void**)&p_feat, g_feat);
    cudaGetSymbolAddress((void**)&p_start, g_start);

    const int Kd[3] = {F_IN_D, 256, 256};
    const int Hh[3] = {4, 4, 1};

    // GEMM layer0 at launch index 3 so the ncu window lands on it.
    k_zero_i<<<cdiv(N, 256), 256>>>(p_deg, N);
    k_deg<<<cdiv(ET, 256), 256>>>(ei, E, ET, p_deg);
    k_scan<<<1, 1024>>>(p_deg, p_rowptr, p_cursor, N);
    {
        dim3 gg(cdiv(N, 128), 4);
        k_gemm_tc<false><<<gg, 256>>>(x, W[0], p_h, N, Kd[0], 256, N,
                                      nullptr, nullptr, nullptr, nullptr,
                                      Asr[0], Ads[0], p_es, p_ed);
    }
    k_fill<<<cdiv(ET, 256), 256>>>(ei, E, ET, p_cursor, p_csrc);
    k_ranges<<<1, 128>>>(batch, N, p_start, p_feat, p_stat);

    for (int li = 0; li < 3; li++) {
        int HD = (li < 2) ? 256 : 128;
        float* bnsum = p_stat + li * 2 * HD_MAX;
        float* bnsq = bnsum + HD_MAX;
        if (li > 0) {
            float* psum = p_stat + (li - 1) * 2 * HD_MAX;
            float* psq = psum + HD_MAX;
            dim3 gg(cdiv(N, 128), HD / 64);
            k_gemm_tc<true><<<gg, 256>>>(p_o, W[li], p_h, N, Kd[li], HD, N,
                                         psum, psq, Ga[li - 1], Be[li - 1],
                                         Asr[li], Ads[li], p_es, p_ed);
        }

        int aggBlocks = cdiv(N * 32, 256);
        if (Hh[li] == 4) {
            k_agg_fused<4, 64><<<aggBlocks, 256>>>(p_h, p_es, p_ed, p_rowptr, p_csrc,
                                                   Bi[li], p_o, bnsum, bnsq, N);
        } else {
            k_agg_fused<1, 128><<<aggBlocks, 256>>>(p_h, p_es, p_ed, p_rowptr, p_csrc,
                                                    Bi[li], p_o, bnsum, bnsq, N);
        }
    }

    // --- pooling + heads (layer-2 BN folded into pool) ---
    {
        float* bnsum2 = p_stat + 2 * 2 * HD_MAX;
        float* bnsq2 = bnsum2 + HD_MAX;
        dim3 pg(G_GRAPHS, 4);
        k_pool<<<pg, 512>>>(p_o, p_start, bnsum2, bnsq2, Ga[2], Be[2], N, p_feat);
    }
    k_heads<<<G_GRAPHS, 128>>>(p_feat, p_start, clfW, clfb, dW1, db1, dW2, db2,
                               (float*)d_out);
}

// round 13
// speedup vs baseline: 1.1613x; 1.1613x over previous
#include <cuda_runtime.h>
#include <cuda_fp16.h>
#include <math.h>
#include <stdint.h>

#define NEG_SLOPE 0.2f
#define EPS_BN 1e-5f
#define N_NODES 20000
#define F_IN_D 128
#define E_EDGES 320000
#define E_TOT (E_EDGES + N_NODES)
#define HD_MAX 256
#define G_GRAPHS 64
#define OUT_DIM 128
#define NCLS_D 10

// ---------------- scratch ----------------
__device__ __half g_h[N_NODES * HD_MAX];          // GEMM output, fp16 (gather source)
__device__ float g_o[N_NODES * HD_MAX];           // agg output (pre-BN), fp32
__device__ float g_es[N_NODES * 4];               // per-(node, column-block) partials
__device__ float g_ed[N_NODES * 4];
__device__ int   g_deg[N_NODES];
__device__ int   g_rowptr[N_NODES + 1];
__device__ int   g_cursor[N_NODES];
__device__ int   g_csrc[E_TOT];
__device__ float g_bnstat[3 * 2 * HD_MAX];
__device__ float g_feat[G_GRAPHS * OUT_DIM];
__device__ int   g_start[G_GRAPHS + 1];

// ---------------- utility ----------------
__global__ void k_zero_i(int* p, int n) {
    int i = blockIdx.x * blockDim.x + threadIdx.x;
    if (i < n) p[i] = 0;
}

// ---------------- CSR build ----------------
__global__ void k_deg(const int* __restrict__ ei, int E, int ET, int* __restrict__ deg) {
    int e = blockIdx.x * blockDim.x + threadIdx.x;
    if (e >= ET) return;
    int d = (e < E) ? ei[E + e] : (e - E);
    atomicAdd(&deg[d], 1);
}

__global__ void k_scan(const int* __restrict__ deg, int* __restrict__ rowptr,
                       int* __restrict__ cursor, int n) {
    __shared__ int sh[1024];
    int t = threadIdx.x;
    int items = (n + 1023) / 1024;
    int b0 = t * items;
    int loc = 0;
    for (int i = 0; i < items; i++) {
        int idx = b0 + i;
        if (idx < n) loc += deg[idx];
    }
    sh[t] = loc;
    __syncthreads();
    for (int off = 1; off < 1024; off <<= 1) {
        int v = (t >= off) ? sh[t - off] : 0;
        __syncthreads();
        sh[t] += v;
        __syncthreads();
    }
    int run = sh[t] - loc;
    for (int i = 0; i < items; i++) {
        int idx = b0 + i;
        if (idx < n) {
            rowptr[idx] = run;
            cursor[idx] = run;
            run += deg[idx];
        }
    }
    if (t == 1023) rowptr[n] = sh[1023];
}

__global__ void k_fill(const int* __restrict__ ei, int E, int ET,
                       int* __restrict__ cursor, int* __restrict__ csrc) {
    int e = blockIdx.x * blockDim.x + threadIdx.x;
    if (e >= ET) return;
    int s, d;
    if (e < E) { s = ei[e]; d = ei[E + e]; }
    else { s = e - E; d = e - E; }
    int pos = atomicAdd(&cursor[d], 1);
    csrc[pos] = s;
}

// graph ranges (batch sorted); also zero feat + bn stat accumulators
__global__ void k_ranges(const int* __restrict__ batch, int n, int* __restrict__ start,
                         float* __restrict__ feat, float* __restrict__ stat) {
    int g = threadIdx.x;
    for (int i = g; i < G_GRAPHS * OUT_DIM; i += 128) feat[i] = 0.f;
    for (int i = g; i < 3 * 2 * HD_MAX; i += 128) stat[i] = 0.f;
    if (g > G_GRAPHS) return;
    if (g == G_GRAPHS) { start[G_GRAPHS] = n; return; }
    int lo = 0, hi = n;
    while (lo < hi) {
        int mid = (lo + hi) >> 1;
        if (batch[mid] < g) lo = mid + 1; else hi = mid;
    }
    start[g] = lo;
}

// ---------------- fp16 helpers ----------------
__device__ __forceinline__ uint32_t pack_h16(float x0, float x1) {
    __half2 h = __floats2half2_rn(x0, x1);
    return *(uint32_t*)&h;
}
__device__ __forceinline__ void mma_fp16(float* c, const uint32_t* a, uint32_t b0, uint32_t b1) {
    asm volatile(
        "mma.sync.aligned.m16n8k16.row.col.f32.f16.f16.f32 "
        "{%0,%1,%2,%3}, {%4,%5,%6,%7}, {%8,%9}, {%0,%1,%2,%3};"
        : "+f"(c[0]), "+f"(c[1]), "+f"(c[2]), "+f"(c[3])
        : "r"(a[0]), "r"(a[1]), "r"(a[2]), "r"(a[3]), "r"(b0), "r"(b1));
}

// ---------------- Tensor-core GEMM: plain fp16, 128x64 tiles, fp16 output ----------
// Single-MMA path (A, W quantized to fp16; fp32 accumulate). Fused BN(prev)+ReLU on
// A load; fused attention-score partials per column block.
#define APAD 136
#define BPAD 72
template <bool FUSE>
__global__ __launch_bounds__(256, 3) void k_gemm_tc(const float* __restrict__ A,
                                                    const float* __restrict__ B,
                                                    __half* __restrict__ C,
                                                    int M, int K, int Nd, int nNodes,
                                                    const float* __restrict__ bnsum,
                                                    const float* __restrict__ bnsq,
                                                    const float* __restrict__ gamma,
                                                    const float* __restrict__ beta,
                                                    const float* __restrict__ asrc,
                                                    const float* __restrict__ adst,
                                                    float* __restrict__ es,
                                                    float* __restrict__ ed) {
    __shared__ __align__(16) uint32_t Ah[2][8][APAD];   // [kpair][row] fp16x2
    __shared__ __align__(16) uint32_t Bh[2][8][BPAD];   // [kpair][col] fp16x2
    __shared__ float ssc[HD_MAX], ssh[HD_MAX];
    __shared__ float sAs[64], sAd[64];
    __shared__ float sE[128][2][2];
    int t = threadIdx.x;
    int bm = blockIdx.x * 128, bn = blockIdx.y * 64;

    if (t < 64) { sAs[t] = asrc[bn + t]; sAd[t] = adst[bn + t]; }
    if (FUSE && t < K) {
        float mu = bnsum[t] / (float)nNodes;
        float var = bnsq[t] / (float)nNodes - mu * mu;
        float sc = gamma[t] * rsqrtf(var + EPS_BN);
        ssc[t] = sc;
        ssh[t] = beta[t] - mu * sc;
    }
    __syncthreads();

    int warp = t >> 5, lane = t & 31;
    int wm = (warp >> 1) * 32, wcol = warp & 1, wn = wcol * 32;
    int gid = lane >> 2, tig = lane & 3;

    int ar = t >> 1, akb = (t & 1) * 8;
    bool avalid = (bm + ar) < M;
    const float* Ap = A + (size_t)(bm + ar) * K + akb;
    const float* Bp = B + (size_t)(warp * 2) * Nd + bn + lane * 2;

    float acc[2][4][4];
#pragma unroll
    for (int mt = 0; mt < 2; mt++)
#pragma unroll
        for (int nt = 0; nt < 4; nt++)
#pragma unroll
            for (int c = 0; c < 4; c++) acc[mt][nt][c] = 0.f;

    float4 a0, a1;
    float2 b0, b1;

    auto stage = [&](int buf, int k0) {
        float v[8] = {a0.x, a0.y, a0.z, a0.w, a1.x, a1.y, a1.z, a1.w};
        if (FUSE) {
#pragma unroll
            for (int j = 0; j < 8; j++)
                v[j] = fmaxf(v[j] * ssc[k0 + akb + j] + ssh[k0 + akb + j], 0.f);
        }
#pragma unroll
        for (int j2 = 0; j2 < 4; j2++)
            Ah[buf][(akb >> 1) + j2][ar] = pack_h16(v[2 * j2], v[2 * j2 + 1]);
        Bh[buf][warp][lane * 2]     = pack_h16(b0.x, b1.x);
        Bh[buf][warp][lane * 2 + 1] = pack_h16(b0.y, b1.y);
    };

    if (avalid) { a0 = *(const float4*)Ap; a1 = *(const float4*)(Ap + 4); }
    else { a0 = make_float4(0, 0, 0, 0); a1 = a0; }
    b0 = *(const float2*)Bp;
    b1 = *(const float2*)(Bp + Nd);
    stage(0, 0);
    __syncthreads();

    int nk = K >> 4;
    for (int kt = 0; kt < nk; kt++) {
        int buf = kt & 1;
        if (kt + 1 < nk) {
            int k0 = (kt + 1) << 4;
            if (avalid) { a0 = *(const float4*)(Ap + k0); a1 = *(const float4*)(Ap + k0 + 4); }
            else { a0 = make_float4(0, 0, 0, 0); a1 = a0; }
            b0 = *(const float2*)(Bp + (size_t)k0 * Nd);
            b1 = *(const float2*)(Bp + (size_t)(k0 + 1) * Nd);
        }

        uint32_t fbh[4][2];
#pragma unroll
        for (int nt = 0; nt < 4; nt++) {
            int c0 = wn + nt * 8 + gid;
            fbh[nt][0] = Bh[buf][tig][c0];
            fbh[nt][1] = Bh[buf][tig + 4][c0];
        }
#pragma unroll
        for (int mt = 0; mt < 2; mt++) {
            int r0i = wm + mt * 16 + gid;
            uint32_t ah[4];
            ah[0] = Ah[buf][tig][r0i];
            ah[1] = Ah[buf][tig][r0i + 8];
            ah[2] = Ah[buf][tig + 4][r0i];
            ah[3] = Ah[buf][tig + 4][r0i + 8];
#pragma unroll
            for (int nt = 0; nt < 4; nt++)
                mma_fp16(acc[mt][nt], ah, fbh[nt][0], fbh[nt][1]);
        }

        if (kt + 1 < nk) {
            int k0 = (kt + 1) << 4;
            stage(buf ^ 1, k0);
        }
        __syncthreads();
    }

    // ---- epilogue: store C (fp16) + attention-score partials ----
    uint32_t* Cb = (uint32_t*)C;
#pragma unroll
    for (int mt = 0; mt < 2; mt++) {
        int r0i = bm + wm + mt * 16 + gid;
        int r1i = r0i + 8;
#pragma unroll
        for (int nt = 0; nt < 4; nt++) {
            int cc = bn + wn + nt * 8 + tig * 2;
            if (r0i < M) Cb[((size_t)r0i * Nd + cc) >> 1] =
                pack_h16(acc[mt][nt][0], acc[mt][nt][1]);
            if (r1i < M) Cb[((size_t)r1i * Nd + cc) >> 1] =
                pack_h16(acc[mt][nt][2], acc[mt][nt][3]);
        }
#pragma unroll
        for (int half = 0; half < 2; half++) {
            float pes = 0.f, ped = 0.f;
#pragma unroll
            for (int nt = 0; nt < 4; nt++) {
#pragma unroll
                for (int j = 0; j < 2; j++) {
                    int cl = wn + nt * 8 + tig * 2 + j;
                    float v = acc[mt][nt][half * 2 + j];
                    pes += v * sAs[cl];
                    ped += v * sAd[cl];
                }
            }
            pes += __shfl_xor_sync(0xffffffffu, pes, 1);
            pes += __shfl_xor_sync(0xffffffffu, pes, 2);
            ped += __shfl_xor_sync(0xffffffffu, ped, 1);
            ped += __shfl_xor_sync(0xffffffffu, ped, 2);
            if (tig == 0) {
                int r = wm + mt * 16 + gid + half * 8;
                sE[r][wcol][0] = pes;
                sE[r][wcol][1] = ped;
            }
        }
    }
    __syncthreads();
    if (t < 128) {
        int row = bm + t;
        if (row < M) {
            es[row * 4 + blockIdx.y] = sE[t][0][0] + sE[t][1][0];
            ed[row * 4 + blockIdx.y] = sE[t][0][1] + sE[t][1][1];
        }
    }
}

// ---------------- single-pass softmax + aggregation (fp16 gather) + BN stats --------
template <int H, int D>
__global__ __launch_bounds__(256) void k_agg_fused(
        const __half* __restrict__ h, const float* __restrict__ es,
        const float* __restrict__ ed, const int* __restrict__ rowptr,
        const int* __restrict__ csrc, const float* __restrict__ bias,
        float* __restrict__ outp, float* __restrict__ bnsum,
        float* __restrict__ bnsq, int n) {
    constexpr int HD = H * D, PL = HD / 32, NV = PL / 4;
    __shared__ float sm8[8][HD];
    int t = threadIdx.x;
    int node = (blockIdx.x * 256 + t) >> 5;
    int lane = t & 31;
    int warp = t >> 5;
    const int hme = (lane * PL) / D;

    float4 res[NV];
#pragma unroll
    for (int q = 0; q < NV; q++) res[q] = make_float4(0.f, 0.f, 0.f, 0.f);

    if (node < n) {
        float edme;
        if (H == 1) edme = ed[node * 4] + ed[node * 4 + 1];
        else        edme = ed[node * 4 + hme];
        int p0 = rowptr[node], p1 = rowptr[node + 1];
        float4 acc[NV];
#pragma unroll
        for (int q = 0; q < NV; q++) acc[q] = make_float4(0.f, 0.f, 0.f, 0.f);
        float z = 0.f;
#pragma unroll 2
        for (int p = p0; p < p1; p++) {
            int s = csrc[p];
            float e;
            if (H == 1) {
                float2 e2 = *(const float2*)&es[s * 4];
                e = e2.x + e2.y + edme;
            } else {
                e = es[s * 4 + hme] + edme;
            }
            e = (e > 0.f) ? e : NEG_SLOPE * e;
            float w = __expf(e);
            z += w;
            const __half* hs = h + (size_t)s * HD + lane * PL;
            uint32_t u[PL / 2];
            if (PL == 8) *(uint4*)u = *(const uint4*)hs;
            else         *(uint2*)u = *(const uint2*)hs;
#pragma unroll
            for (int q = 0; q < NV; q++) {
                float2 f0 = __half22float2(*(__half2*)&u[q * 2]);
                float2 f1 = __half22float2(*(__half2*)&u[q * 2 + 1]);
                acc[q].x += f0.x * w; acc[q].y += f0.y * w;
                acc[q].z += f1.x * w; acc[q].w += f1.y * w;
            }
        }
        float iz = 1.f / z;
        const float4* bb = (const float4*)(bias + lane * PL);
        float4* op = (float4*)(outp + (size_t)node * HD + lane * PL);
#pragma unroll
        for (int q = 0; q < NV; q++) {
            float4 b = bb[q];
            res[q] = make_float4(acc[q].x * iz + b.x, acc[q].y * iz + b.y,
                                 acc[q].z * iz + b.z, acc[q].w * iz + b.w);
            op[q] = res[q];
        }
    }

    // BN stats: stage rows in smem, channel-wise reduce, 2 global atomics/ch/block
#pragma unroll
    for (int q = 0; q < NV; q++)
        *(float4*)&sm8[warp][lane * PL + q * 4] = res[q];
    __syncthreads();
    if (t < HD) {
        float s = 0.f, q2 = 0.f;
#pragma unroll
        for (int w = 0; w < 8; w++) {
            float v = sm8[w][t];
            s += v;
            q2 += v * v;
        }
        atomicAdd(&bnsum[t], s);
        atomicAdd(&bnsq[t], q2);
    }
}

// ---------------- pooling (BN scale/shift computed in-block from stats) -------------
__global__ void k_pool(const float* __restrict__ o, const int* __restrict__ start,
                       const float* __restrict__ bnsum, const float* __restrict__ bnsq,
                       const float* __restrict__ gamma, const float* __restrict__ beta,
                       int n, float* __restrict__ feat) {
    __shared__ float sm[4][OUT_DIM];
    __shared__ float ssc[OUT_DIM], ssh[OUT_DIM];
    int c = threadIdx.x & 127;
    int rgrp = threadIdx.x >> 7;
    if (threadIdx.x < OUT_DIM) {
        float mu = bnsum[c] / (float)n;
        float var = bnsq[c] / (float)n - mu * mu;
        float sc2 = gamma[c] * rsqrtf(var + EPS_BN);
        ssc[c] = sc2;
        ssh[c] = beta[c] - mu * sc2;
    }
    __syncthreads();
    int g = blockIdx.x;
    int part = blockIdx.y;
    int s0 = start[g], s1 = start[g + 1];
    int len = s1 - s0;
    int chunk = (len + 3) >> 2;
    int r0 = s0 + part * chunk;
    int r1 = min(s1, r0 + chunk);
    float sc = ssc[c], sh = ssh[c];
    float sum = 0.f;
    for (int r = r0 + rgrp; r < r1; r += 4) {
        float v = o[(size_t)r * OUT_DIM + c];
        sum += fmaxf(v * sc + sh, 0.f);
    }
    sm[rgrp][c] = sum;
    __syncthreads();
    if (threadIdx.x < OUT_DIM) {
        float s = sm[0][c] + sm[1][c] + sm[2][c] + sm[3][c];
        atomicAdd(&feat[g * OUT_DIM + c], s);
    }
}

// ---------------- heads ----------------
__global__ void k_heads(const float* __restrict__ featsum, const int* __restrict__ start,
                        const float* __restrict__ clfW, const float* __restrict__ clfb,
                        const float* __restrict__ dW1, const float* __restrict__ db1,
                        const float* __restrict__ dW2, const float* __restrict__ db2,
                        float* __restrict__ out) {
    __shared__ float f[OUT_DIM];
    __shared__ float dh[64];
    int g = blockIdx.x, t = threadIdx.x;
    float c = (float)max(start[g + 1] - start[g], 1);
    f[t] = featsum[g * OUT_DIM + t] / c;
    out[G_GRAPHS * NCLS_D + G_GRAPHS * 2 + g * OUT_DIM + t] = f[t];
    __syncthreads();
    if (t < 64) {
        float s = db1[t];
        for (int k = 0; k < OUT_DIM; k++) s += f[k] * dW1[k * 64 + t];
        dh[t] = fmaxf(s, 0.f);
    }
    if (t < NCLS_D) {
        float s = clfb[t];
        for (int k = 0; k < OUT_DIM; k++) s += f[k] * clfW[k * NCLS_D + t];
        out[g * NCLS_D + t] = s;
    }
    __syncthreads();
    if (t < 2) {
        float s = db2[t];
        for (int k = 0; k < 64; k++) s += dh[k] * dW2[k * 2 + t];
        out[G_GRAPHS * NCLS_D + g * 2 + t] = s;
    }
}

// ---------------- launch ----------------
static inline int cdiv(int a, int b) { return (a + b - 1) / b; }

extern "C" void kernel_launch(void* const* d_in, const int* in_sizes, int n_in,
                              void* d_out, int out_size) {
    const float* x = (const float*)d_in[0];
    const int* ei = (const int*)d_in[1];
    const int* batch = (const int*)d_in[2];
    const float* W[3]   = {(const float*)d_in[3],  (const float*)d_in[9],  (const float*)d_in[15]};
    const float* Asr[3] = {(const float*)d_in[4],  (const float*)d_in[10], (const float*)d_in[16]};
    const float* Ads[3] = {(const float*)d_in[5],  (const float*)d_in[11], (const float*)d_in[17]};
    const float* Bi[3]  = {(const float*)d_in[6],  (const float*)d_in[12], (const float*)d_in[18]};
    const float* Ga[3]  = {(const float*)d_in[7],  (const float*)d_in[13], (const float*)d_in[19]};
    const float* Be[3]  = {(const float*)d_in[8],  (const float*)d_in[14], (const float*)d_in[20]};
    const float* clfW = (const float*)d_in[21];
    const float* clfb = (const float*)d_in[22];
    const float* dW1 = (const float*)d_in[23];
    const float* db1 = (const float*)d_in[24];
    const float* dW2 = (const float*)d_in[25];
    const float* db2 = (const float*)d_in[26];

    int N = in_sizes[0] / F_IN_D;
    int E = in_sizes[1] / 2;
    int ET = E + N;

    float *p_o, *p_es, *p_ed, *p_stat, *p_feat;
    __half* p_h;
    int *p_deg, *p_rowptr, *p_cursor, *p_csrc, *p_start;
    cudaGetSymbolAddress((void**)&p_h, g_h);
    cudaGetSymbolAddress((void**)&p_o, g_o);
    cudaGetSymbolAddress((void**)&p_es, g_es);
    cudaGetSymbolAddress((void**)&p_ed, g_ed);
    cudaGetSymbolAddress((void**)&p_deg, g_deg);
    cudaGetSymbolAddress((void**)&p_rowptr, g_rowptr);
    cudaGetSymbolAddress((void**)&p_cursor, g_cursor);
    cudaGetSymbolAddress((void**)&p_csrc, g_csrc);
    cudaGetSymbolAddress((void**)&p_stat, g_bnstat);
    cudaGetSymbolAddress((void**)&p_feat, g_feat);
    cudaGetSymbolAddress((void**)&p_start, g_start);

    const int Kd[3] = {F_IN_D, 256, 256};
    const int Hh[3] = {4, 4, 1};

    // GEMM layer0 at launch index 3 so the ncu window lands on it.
    k_zero_i<<<cdiv(N, 256), 256>>>(p_deg, N);
    k_deg<<<cdiv(ET, 256), 256>>>(ei, E, ET, p_deg);
    k_scan<<<1, 1024>>>(p_deg, p_rowptr, p_cursor, N);
    {
        dim3 gg(cdiv(N, 128), 4);
        k_gemm_tc<false><<<gg, 256>>>(x, W[0], p_h, N, Kd[0], 256, N,
                                      nullptr, nullptr, nullptr, nullptr,
                                      Asr[0], Ads[0], p_es, p_ed);
    }
    k_fill<<<cdiv(ET, 256), 256>>>(ei, E, ET, p_cursor, p_csrc);
    k_ranges<<<1, 128>>>(batch, N, p_start, p_feat, p_stat);

    for (int li = 0; li < 3; li++) {
        int HD = (li < 2) ? 256 : 128;
        float* bnsum = p_stat + li * 2 * HD_MAX;
        float* bnsq = bnsum + HD_MAX;
        if (li > 0) {
            float* psum = p_stat + (li - 1) * 2 * HD_MAX;
            float* psq = psum + HD_MAX;
            dim3 gg(cdiv(N, 128), HD / 64);
            k_gemm_tc<true><<<gg, 256>>>(p_o, W[li], p_h, N, Kd[li], HD, N,
                                         psum, psq, Ga[li - 1], Be[li - 1],
                                         Asr[li], Ads[li], p_es, p_ed);
        }

        int aggBlocks = cdiv(N * 32, 256);
        if (Hh[li] == 4) {
            k_agg_fused<4, 64><<<aggBlocks, 256>>>(p_h, p_es, p_ed, p_rowptr, p_csrc,
                                                   Bi[li], p_o, bnsum, bnsq, N);
        } else {
            k_agg_fused<1, 128><<<aggBlocks, 256>>>(p_h, p_es, p_ed, p_rowptr, p_csrc,
                                                    Bi[li], p_o, bnsum, bnsq, N);
        }
    }

    // --- pooling + heads (layer-2 BN folded into pool) ---
    {
        float* bnsum2 = p_stat + 2 * 2 * HD_MAX;
        float* bnsq2 = bnsum2 + HD_MAX;
        dim3 pg(G_GRAPHS, 4);
        k_pool<<<pg, 512>>>(p_o, p_start, bnsum2, bnsq2, Ga[2], Be[2], N, p_feat);
    }
    k_heads<<<G_GRAPHS, 128>>>(p_feat, p_start, clfW, clfb, dW1, db1, dW2, db2,
                               (float*)d_out);
}

// round 14
// speedup vs baseline: 1.1648x; 1.0030x over previous
#include <cuda_runtime.h>
#include <cuda_fp16.h>
#include <math.h>
#include <stdint.h>

#define NEG_SLOPE 0.2f
#define EPS_BN 1e-5f
#define N_NODES 20000
#define F_IN_D 128
#define E_EDGES 320000
#define E_TOT (E_EDGES + N_NODES)
#define HD_MAX 256
#define G_GRAPHS 64
#define OUT_DIM 128
#define NCLS_D 10

// ---------------- scratch ----------------
__device__ __half g_h[N_NODES * HD_MAX];          // GEMM output, fp16 (gather source)
__device__ float g_o[N_NODES * HD_MAX];           // agg output (pre-BN), fp32
__device__ float g_es[N_NODES * 4];               // per-(node, column-block) partials
__device__ float g_ed[N_NODES * 4];
__device__ int   g_deg[N_NODES];
__device__ int   g_rowptr[N_NODES + 1];
__device__ int   g_cursor[N_NODES];
__device__ int   g_csrc[E_TOT];
__device__ float g_bnstat[3 * 2 * HD_MAX];
__device__ float g_feat[G_GRAPHS * OUT_DIM];
__device__ int   g_start[G_GRAPHS + 1];

// ---------------- utility ----------------
__global__ void k_zero_i(int* p, int n) {
    int i = blockIdx.x * blockDim.x + threadIdx.x;
    if (i < n) p[i] = 0;
}

// ---------------- CSR build ----------------
__global__ void k_deg(const int* __restrict__ ei, int E, int ET, int* __restrict__ deg) {
    int e = blockIdx.x * blockDim.x + threadIdx.x;
    if (e >= ET) return;
    int d = (e < E) ? ei[E + e] : (e - E);
    atomicAdd(&deg[d], 1);
}

// scan + graph ranges + feat/stat zero (all single-block setup work)
__global__ void k_scan(const int* __restrict__ deg, int* __restrict__ rowptr,
                       int* __restrict__ cursor, int n,
                       const int* __restrict__ batch, int* __restrict__ start,
                       float* __restrict__ feat, float* __restrict__ stat) {
    __shared__ int sh[1024];
    int t = threadIdx.x;
    int items = (n + 1023) / 1024;
    int b0 = t * items;
    int loc = 0;
    for (int i = 0; i < items; i++) {
        int idx = b0 + i;
        if (idx < n) loc += deg[idx];
    }
    sh[t] = loc;
    __syncthreads();
    for (int off = 1; off < 1024; off <<= 1) {
        int v = (t >= off) ? sh[t - off] : 0;
        __syncthreads();
        sh[t] += v;
        __syncthreads();
    }
    int run = sh[t] - loc;
    for (int i = 0; i < items; i++) {
        int idx = b0 + i;
        if (idx < n) {
            rowptr[idx] = run;
            cursor[idx] = run;
            run += deg[idx];
        }
    }
    if (t == 1023) rowptr[n] = sh[1023];

    // extra setup work (independent of scan)
    for (int i = t; i < G_GRAPHS * OUT_DIM; i += 1024) feat[i] = 0.f;
    for (int i = t; i < 3 * 2 * HD_MAX; i += 1024) stat[i] = 0.f;
    if (t <= G_GRAPHS) {
        if (t == G_GRAPHS) start[G_GRAPHS] = n;
        else {
            int lo = 0, hi = n;
            while (lo < hi) {
                int mid = (lo + hi) >> 1;
                if (batch[mid] < t) lo = mid + 1; else hi = mid;
            }
            start[t] = lo;
        }
    }
}

__global__ void k_fill(const int* __restrict__ ei, int E, int ET,
                       int* __restrict__ cursor, int* __restrict__ csrc) {
    int e = blockIdx.x * blockDim.x + threadIdx.x;
    if (e >= ET) return;
    int s, d;
    if (e < E) { s = ei[e]; d = ei[E + e]; }
    else { s = e - E; d = e - E; }
    int pos = atomicAdd(&cursor[d], 1);
    csrc[pos] = s;
}

// ---------------- fp16 helpers ----------------
__device__ __forceinline__ uint32_t pack_h16(float x0, float x1) {
    __half2 h = __floats2half2_rn(x0, x1);
    return *(uint32_t*)&h;
}
__device__ __forceinline__ void mma_fp16(float* c, const uint32_t* a, uint32_t b0, uint32_t b1) {
    asm volatile(
        "mma.sync.aligned.m16n8k16.row.col.f32.f16.f16.f32 "
        "{%0,%1,%2,%3}, {%4,%5,%6,%7}, {%8,%9}, {%0,%1,%2,%3};"
        : "+f"(c[0]), "+f"(c[1]), "+f"(c[2]), "+f"(c[3])
        : "r"(a[0]), "r"(a[1]), "r"(a[2]), "r"(a[3]), "r"(b0), "r"(b1));
}

// ---------------- Tensor-core GEMM: plain fp16, 128x64 tiles, KT=32 ----------------
#define APAD 136
#define BPAD 72
template <bool FUSE>
__global__ __launch_bounds__(256, 3) void k_gemm_tc(const float* __restrict__ A,
                                                    const float* __restrict__ B,
                                                    __half* __restrict__ C,
                                                    int M, int K, int Nd, int nNodes,
                                                    const float* __restrict__ bnsum,
                                                    const float* __restrict__ bnsq,
                                                    const float* __restrict__ gamma,
                                                    const float* __restrict__ beta,
                                                    const float* __restrict__ asrc,
                                                    const float* __restrict__ adst,
                                                    float* __restrict__ es,
                                                    float* __restrict__ ed) {
    __shared__ __align__(16) uint32_t Ah[2][16][APAD];  // [kpair][row] fp16x2
    __shared__ __align__(16) uint32_t Bh[2][16][BPAD];  // [kpair][col] fp16x2
    __shared__ float ssc[HD_MAX], ssh[HD_MAX];
    __shared__ float sAs[64], sAd[64];
    __shared__ float sE[128][2][2];
    int t = threadIdx.x;
    int bm = blockIdx.x * 128, bn = blockIdx.y * 64;

    if (t < 64) { sAs[t] = asrc[bn + t]; sAd[t] = adst[bn + t]; }
    if (FUSE && t < K) {
        float mu = bnsum[t] / (float)nNodes;
        float var = bnsq[t] / (float)nNodes - mu * mu;
        float sc = gamma[t] * rsqrtf(var + EPS_BN);
        ssc[t] = sc;
        ssh[t] = beta[t] - mu * sc;
    }
    __syncthreads();

    int warp = t >> 5, lane = t & 31;
    int wm = (warp >> 1) * 32, wcol = warp & 1, wn = wcol * 32;
    int gid = lane >> 2, tig = lane & 3;

    // A staging: row ar (0..127), k-offsets akb..akb+15
    int ar = t >> 1, akb = (t & 1) * 16;
    bool avalid = (bm + ar) < M;
    const float* Ap = A + (size_t)(bm + ar) * K + akb;
    // B staging: warp w loads k-rows 4w..4w+3; lane covers cols lane*2, lane*2+1
    const float* Bp = B + (size_t)(warp * 4) * Nd + bn + lane * 2;

    float acc[2][4][4];
#pragma unroll
    for (int mt = 0; mt < 2; mt++)
#pragma unroll
        for (int nt = 0; nt < 4; nt++)
#pragma unroll
            for (int c = 0; c < 4; c++) acc[mt][nt][c] = 0.f;

    float4 a0, a1, a2, a3;
    float2 b0, b1, b2, b3;

    auto gload = [&](int k0) {
        if (avalid) {
            a0 = *(const float4*)(Ap + k0);
            a1 = *(const float4*)(Ap + k0 + 4);
            a2 = *(const float4*)(Ap + k0 + 8);
            a3 = *(const float4*)(Ap + k0 + 12);
        } else {
            a0 = make_float4(0, 0, 0, 0); a1 = a0; a2 = a0; a3 = a0;
        }
        b0 = *(const float2*)(Bp + (size_t)k0 * Nd);
        b1 = *(const float2*)(Bp + (size_t)(k0 + 1) * Nd);
        b2 = *(const float2*)(Bp + (size_t)(k0 + 2) * Nd);
        b3 = *(const float2*)(Bp + (size_t)(k0 + 3) * Nd);
    };

    auto stage = [&](int buf, int k0) {
        float v[16] = {a0.x, a0.y, a0.z, a0.w, a1.x, a1.y, a1.z, a1.w,
                       a2.x, a2.y, a2.z, a2.w, a3.x, a3.y, a3.z, a3.w};
        if (FUSE) {
#pragma unroll
            for (int j = 0; j < 16; j++)
                v[j] = fmaxf(v[j] * ssc[k0 + akb + j] + ssh[k0 + akb + j], 0.f);
        }
#pragma unroll
        for (int j2 = 0; j2 < 8; j2++)
            Ah[buf][(akb >> 1) + j2][ar] = pack_h16(v[2 * j2], v[2 * j2 + 1]);
        Bh[buf][warp * 2][lane * 2]         = pack_h16(b0.x, b1.x);
        Bh[buf][warp * 2][lane * 2 + 1]     = pack_h16(b0.y, b1.y);
        Bh[buf][warp * 2 + 1][lane * 2]     = pack_h16(b2.x, b3.x);
        Bh[buf][warp * 2 + 1][lane * 2 + 1] = pack_h16(b2.y, b3.y);
    };

    gload(0);
    stage(0, 0);
    __syncthreads();

    int nk = K >> 5;
    for (int kt = 0; kt < nk; kt++) {
        int buf = kt & 1;
        if (kt + 1 < nk) gload((kt + 1) << 5);

#pragma unroll
        for (int ks = 0; ks < 2; ks++) {
            uint32_t fbh[4][2];
#pragma unroll
            for (int nt = 0; nt < 4; nt++) {
                int c0 = wn + nt * 8 + gid;
                fbh[nt][0] = Bh[buf][ks * 8 + tig][c0];
                fbh[nt][1] = Bh[buf][ks * 8 + tig + 4][c0];
            }
#pragma unroll
            for (int mt = 0; mt < 2; mt++) {
                int r0i = wm + mt * 16 + gid;
                uint32_t ah[4];
                ah[0] = Ah[buf][ks * 8 + tig][r0i];
                ah[1] = Ah[buf][ks * 8 + tig][r0i + 8];
                ah[2] = Ah[buf][ks * 8 + tig + 4][r0i];
                ah[3] = Ah[buf][ks * 8 + tig + 4][r0i + 8];
#pragma unroll
                for (int nt = 0; nt < 4; nt++)
                    mma_fp16(acc[mt][nt], ah, fbh[nt][0], fbh[nt][1]);
            }
        }

        if (kt + 1 < nk) stage(buf ^ 1, (kt + 1) << 5);
        __syncthreads();
    }

    // ---- epilogue: store C (fp16) + attention-score partials ----
    uint32_t* Cb = (uint32_t*)C;
#pragma unroll
    for (int mt = 0; mt < 2; mt++) {
        int r0i = bm + wm + mt * 16 + gid;
        int r1i = r0i + 8;
#pragma unroll
        for (int nt = 0; nt < 4; nt++) {
            int cc = bn + wn + nt * 8 + tig * 2;
            if (r0i < M) Cb[((size_t)r0i * Nd + cc) >> 1] =
                pack_h16(acc[mt][nt][0], acc[mt][nt][1]);
            if (r1i < M) Cb[((size_t)r1i * Nd + cc) >> 1] =
                pack_h16(acc[mt][nt][2], acc[mt][nt][3]);
        }
#pragma unroll
        for (int half = 0; half < 2; half++) {
            float pes = 0.f, ped = 0.f;
#pragma unroll
            for (int nt = 0; nt < 4; nt++) {
#pragma unroll
                for (int j = 0; j < 2; j++) {
                    int cl = wn + nt * 8 + tig * 2 + j;
                    float v = acc[mt][nt][half * 2 + j];
                    pes += v * sAs[cl];
                    ped += v * sAd[cl];
                }
            }
            pes += __shfl_xor_sync(0xffffffffu, pes, 1);
            pes += __shfl_xor_sync(0xffffffffu, pes, 2);
            ped += __shfl_xor_sync(0xffffffffu, ped, 1);
            ped += __shfl_xor_sync(0xffffffffu, ped, 2);
            if (tig == 0) {
                int r = wm + mt * 16 + gid + half * 8;
                sE[r][wcol][0] = pes;
                sE[r][wcol][1] = ped;
            }
        }
    }
    __syncthreads();
    if (t < 128) {
        int row = bm + t;
        if (row < M) {
            es[row * 4 + blockIdx.y] = sE[t][0][0] + sE[t][1][0];
            ed[row * 4 + blockIdx.y] = sE[t][0][1] + sE[t][1][1];
        }
    }
}

// ---------------- single-pass softmax + aggregation (fp16 gather) + BN stats --------
template <int H, int D>
__global__ __launch_bounds__(256) void k_agg_fused(
        const __half* __restrict__ h, const float* __restrict__ es,
        const float* __restrict__ ed, const int* __restrict__ rowptr,
        const int* __restrict__ csrc, const float* __restrict__ bias,
        float* __restrict__ outp, float* __restrict__ bnsum,
        float* __restrict__ bnsq, int n) {
    constexpr int HD = H * D, PL = HD / 32, NV = PL / 4;
    __shared__ float sm8[8][HD];
    int t = threadIdx.x;
    int node = (blockIdx.x * 256 + t) >> 5;
    int lane = t & 31;
    int warp = t >> 5;
    const int hme = (lane * PL) / D;

    float4 res[NV];
#pragma unroll
    for (int q = 0; q < NV; q++) res[q] = make_float4(0.f, 0.f, 0.f, 0.f);

    if (node < n) {
        float edme;
        if (H == 1) edme = ed[node * 4] + ed[node * 4 + 1];
        else        edme = ed[node * 4 + hme];
        int p0 = rowptr[node], p1 = rowptr[node + 1];
        float4 acc[NV];
#pragma unroll
        for (int q = 0; q < NV; q++) acc[q] = make_float4(0.f, 0.f, 0.f, 0.f);
        float z = 0.f;
#pragma unroll 2
        for (int p = p0; p < p1; p++) {
            int s = csrc[p];
            float e;
            if (H == 1) {
                float2 e2 = *(const float2*)&es[s * 4];
                e = e2.x + e2.y + edme;
            } else {
                e = es[s * 4 + hme] + edme;
            }
            e = (e > 0.f) ? e : NEG_SLOPE * e;
            float w = __expf(e);
            z += w;
            const __half* hs = h + (size_t)s * HD + lane * PL;
            uint32_t u[PL / 2];
            if (PL == 8) *(uint4*)u = *(const uint4*)hs;
            else         *(uint2*)u = *(const uint2*)hs;
#pragma unroll
            for (int q = 0; q < NV; q++) {
                float2 f0 = __half22float2(*(__half2*)&u[q * 2]);
                float2 f1 = __half22float2(*(__half2*)&u[q * 2 + 1]);
                acc[q].x += f0.x * w; acc[q].y += f0.y * w;
                acc[q].z += f1.x * w; acc[q].w += f1.y * w;
            }
        }
        float iz = 1.f / z;
        const float4* bb = (const float4*)(bias + lane * PL);
        float4* op = (float4*)(outp + (size_t)node * HD + lane * PL);
#pragma unroll
        for (int q = 0; q < NV; q++) {
            float4 b = bb[q];
            res[q] = make_float4(acc[q].x * iz + b.x, acc[q].y * iz + b.y,
                                 acc[q].z * iz + b.z, acc[q].w * iz + b.w);
            op[q] = res[q];
        }
    }

    // BN stats: stage rows in smem, channel-wise reduce, 2 global atomics/ch/block
#pragma unroll
    for (int q = 0; q < NV; q++)
        *(float4*)&sm8[warp][lane * PL + q * 4] = res[q];
    __syncthreads();
    if (t < HD) {
        float s = 0.f, q2 = 0.f;
#pragma unroll
        for (int w = 0; w < 8; w++) {
            float v = sm8[w][t];
            s += v;
            q2 += v * v;
        }
        atomicAdd(&bnsum[t], s);
        atomicAdd(&bnsq[t], q2);
    }
}

// ---------------- pooling (BN scale/shift computed in-block from stats) -------------
__global__ void k_pool(const float* __restrict__ o, const int* __restrict__ start,
                       const float* __restrict__ bnsum, const float* __restrict__ bnsq,
                       const float* __restrict__ gamma, const float* __restrict__ beta,
                       int n, float* __restrict__ feat) {
    __shared__ float sm[4][OUT_DIM];
    __shared__ float ssc[OUT_DIM], ssh[OUT_DIM];
    int c = threadIdx.x & 127;
    int rgrp = threadIdx.x >> 7;
    if (threadIdx.x < OUT_DIM) {
        float mu = bnsum[c] / (float)n;
        float var = bnsq[c] / (float)n - mu * mu;
        float sc2 = gamma[c] * rsqrtf(var + EPS_BN);
        ssc[c] = sc2;
        ssh[c] = beta[c] - mu * sc2;
    }
    __syncthreads();
    int g = blockIdx.x;
    int part = blockIdx.y;
    int s0 = start[g], s1 = start[g + 1];
    int len = s1 - s0;
    int chunk = (len + 3) >> 2;
    int r0 = s0 + part * chunk;
    int r1 = min(s1, r0 + chunk);
    float sc = ssc[c], sh = ssh[c];
    float sum = 0.f;
    for (int r = r0 + rgrp; r < r1; r += 4) {
        float v = o[(size_t)r * OUT_DIM + c];
        sum += fmaxf(v * sc + sh, 0.f);
    }
    sm[rgrp][c] = sum;
    __syncthreads();
    if (threadIdx.x < OUT_DIM) {
        float s = sm[0][c] + sm[1][c] + sm[2][c] + sm[3][c];
        atomicAdd(&feat[g * OUT_DIM + c], s);
    }
}

// ---------------- heads ----------------
__global__ void k_heads(const float* __restrict__ featsum, const int* __restrict__ start,
                        const float* __restrict__ clfW, const float* __restrict__ clfb,
                        const float* __restrict__ dW1, const float* __restrict__ db1,
                        const float* __restrict__ dW2, const float* __restrict__ db2,
                        float* __restrict__ out) {
    __shared__ float f[OUT_DIM];
    __shared__ float dh[64];
    int g = blockIdx.x, t = threadIdx.x;
    float c = (float)max(start[g + 1] - start[g], 1);
    f[t] = featsum[g * OUT_DIM + t] / c;
    out[G_GRAPHS * NCLS_D + G_GRAPHS * 2 + g * OUT_DIM + t] = f[t];
    __syncthreads();
    if (t < 64) {
        float s = db1[t];
        for (int k = 0; k < OUT_DIM; k++) s += f[k] * dW1[k * 64 + t];
        dh[t] = fmaxf(s, 0.f);
    }
    if (t < NCLS_D) {
        float s = clfb[t];
        for (int k = 0; k < OUT_DIM; k++) s += f[k] * clfW[k * NCLS_D + t];
        out[g * NCLS_D + t] = s;
    }
    __syncthreads();
    if (t < 2) {
        float s = db2[t];
        for (int k = 0; k < 64; k++) s += dh[k] * dW2[k * 2 + t];
        out[G_GRAPHS * NCLS_D + g * 2 + t] = s;
    }
}

// ---------------- launch ----------------
static inline int cdiv(int a, int b) { return (a + b - 1) / b; }

extern "C" void kernel_launch(void* const* d_in, const int* in_sizes, int n_in,
                              void* d_out, int out_size) {
    const float* x = (const float*)d_in[0];
    const int* ei = (const int*)d_in[1];
    const int* batch = (const int*)d_in[2];
    const float* W[3]   = {(const float*)d_in[3],  (const float*)d_in[9],  (const float*)d_in[15]};
    const float* Asr[3] = {(const float*)d_in[4],  (const float*)d_in[10], (const float*)d_in[16]};
    const float* Ads[3] = {(const float*)d_in[5],  (const float*)d_in[11], (const float*)d_in[17]};
    const float* Bi[3]  = {(const float*)d_in[6],  (const float*)d_in[12], (const float*)d_in[18]};
    const float* Ga[3]  = {(const float*)d_in[7],  (const float*)d_in[13], (const float*)d_in[19]};
    const float* Be[3]  = {(const float*)d_in[8],  (const float*)d_in[14], (const float*)d_in[20]};
    const float* clfW = (const float*)d_in[21];
    const float* clfb = (const float*)d_in[22];
    const float* dW1 = (const float*)d_in[23];
    const float* db1 = (const float*)d_in[24];
    const float* dW2 = (const float*)d_in[25];
    const float* db2 = (const float*)d_in[26];

    int N = in_sizes[0] / F_IN_D;
    int E = in_sizes[1] / 2;
    int ET = E + N;

    float *p_o, *p_es, *p_ed, *p_stat, *p_feat;
    __half* p_h;
    int *p_deg, *p_rowptr, *p_cursor, *p_csrc, *p_start;
    cudaGetSymbolAddress((void**)&p_h, g_h);
    cudaGetSymbolAddress((void**)&p_o, g_o);
    cudaGetSymbolAddress((void**)&p_es, g_es);
    cudaGetSymbolAddress((void**)&p_ed, g_ed);
    cudaGetSymbolAddress((void**)&p_deg, g_deg);
    cudaGetSymbolAddress((void**)&p_rowptr, g_rowptr);
    cudaGetSymbolAddress((void**)&p_cursor, g_cursor);
    cudaGetSymbolAddress((void**)&p_csrc, g_csrc);
    cudaGetSymbolAddress((void**)&p_stat, g_bnstat);
    cudaGetSymbolAddress((void**)&p_feat, g_feat);
    cudaGetSymbolAddress((void**)&p_start, g_start);

    const int Kd[3] = {F_IN_D, 256, 256};
    const int Hh[3] = {4, 4, 1};

    // GEMM layer0 at launch index 3 so the ncu window lands on it.
    k_zero_i<<<cdiv(N, 256), 256>>>(p_deg, N);
    k_deg<<<cdiv(ET, 256), 256>>>(ei, E, ET, p_deg);
    k_scan<<<1, 1024>>>(p_deg, p_rowptr, p_cursor, N, batch, p_start, p_feat, p_stat);
    {
        dim3 gg(cdiv(N, 128), 4);
        k_gemm_tc<false><<<gg, 256>>>(x, W[0], p_h, N, Kd[0], 256, N,
                                      nullptr, nullptr, nullptr, nullptr,
                                      Asr[0], Ads[0], p_es, p_ed);
    }
    k_fill<<<cdiv(ET, 256), 256>>>(ei, E, ET, p_cursor, p_csrc);

    for (int li = 0; li < 3; li++) {
        int HD = (li < 2) ? 256 : 128;
        float* bnsum = p_stat + li * 2 * HD_MAX;
        float* bnsq = bnsum + HD_MAX;
        if (li > 0) {
            float* psum = p_stat + (li - 1) * 2 * HD_MAX;
            float* psq = psum + HD_MAX;
            dim3 gg(cdiv(N, 128), HD / 64);
            k_gemm_tc<true><<<gg, 256>>>(p_o, W[li], p_h, N, Kd[li], HD, N,
                                         psum, psq, Ga[li - 1], Be[li - 1],
                                         Asr[li], Ads[li], p_es, p_ed);
        }

        int aggBlocks = cdiv(N * 32, 256);
        if (Hh[li] == 4) {
            k_agg_fused<4, 64><<<aggBlocks, 256>>>(p_h, p_es, p_ed, p_rowptr, p_csrc,
                                                   Bi[li], p_o, bnsum, bnsq, N);
        } else {
            k_agg_fused<1, 128><<<aggBlocks, 256>>>(p_h, p_es, p_ed, p_rowptr, p_csrc,
                                                    Bi[li], p_o, bnsum, bnsq, N);
        }
    }

    // --- pooling + heads (layer-2 BN folded into pool) ---
    {
        float* bnsum2 = p_stat + 2 * 2 * HD_MAX;
        float* bnsq2 = bnsum2 + HD_MAX;
        dim3 pg(G_GRAPHS, 4);
        k_pool<<<pg, 512>>>(p_o, p_start, bnsum2, bnsq2, Ga[2], Be[2], N, p_feat);
    }
    k_heads<<<G_GRAPHS, 128>>>(p_feat, p_start, clfW, clfb, dW1, db1, dW2, db2,
                               (float*)d_out);
}

// round 15
// speedup vs baseline: 1.2344x; 1.0598x over previous
#include <cuda_runtime.h>
#include <cuda_fp16.h>
#include <math.h>
#include <stdint.h>

#define NEG_SLOPE 0.2f
#define EPS_BN 1e-5f
#define N_NODES 20000
#define F_IN_D 128
#define E_EDGES 320000
#define E_TOT (E_EDGES + N_NODES)
#define HD_MAX 256
#define G_GRAPHS 64
#define OUT_DIM 128
#define NCLS_D 10

// ---------------- scratch ----------------
__device__ __half g_h[N_NODES * HD_MAX];          // GEMM output, fp16 (gather source)
__device__ __half g_o[N_NODES * HD_MAX];          // agg output (pre-BN), fp16
__device__ float g_es[N_NODES * 4];               // per-(node, column-block) partials
__device__ float g_ed[N_NODES * 4];
__device__ int   g_deg[N_NODES];
__device__ int   g_rowptr[N_NODES + 1];
__device__ int   g_cursor[N_NODES];
__device__ int   g_csrc[E_TOT];
__device__ float g_bnstat[3 * 2 * HD_MAX];
__device__ float g_feat[G_GRAPHS * OUT_DIM];
__device__ int   g_start[G_GRAPHS + 1];

// ---------------- utility ----------------
__global__ void k_zero_i(int* p, int n) {
    int i = blockIdx.x * blockDim.x + threadIdx.x;
    if (i < n) p[i] = 0;
}

// ---------------- CSR build ----------------
__global__ void k_deg(const int* __restrict__ ei, int E, int ET, int* __restrict__ deg) {
    int e = blockIdx.x * blockDim.x + threadIdx.x;
    if (e >= ET) return;
    int d = (e < E) ? ei[E + e] : (e - E);
    atomicAdd(&deg[d], 1);
}

// scan + graph ranges + feat/stat zero (all single-block setup work)
__global__ void k_scan(const int* __restrict__ deg, int* __restrict__ rowptr,
                       int* __restrict__ cursor, int n,
                       const int* __restrict__ batch, int* __restrict__ start,
                       float* __restrict__ feat, float* __restrict__ stat) {
    __shared__ int sh[1024];
    int t = threadIdx.x;
    int items = (n + 1023) / 1024;
    int b0 = t * items;
    int loc = 0;
    for (int i = 0; i < items; i++) {
        int idx = b0 + i;
        if (idx < n) loc += deg[idx];
    }
    sh[t] = loc;
    __syncthreads();
    for (int off = 1; off < 1024; off <<= 1) {
        int v = (t >= off) ? sh[t - off] : 0;
        __syncthreads();
        sh[t] += v;
        __syncthreads();
    }
    int run = sh[t] - loc;
    for (int i = 0; i < items; i++) {
        int idx = b0 + i;
        if (idx < n) {
            rowptr[idx] = run;
            cursor[idx] = run;
            run += deg[idx];
        }
    }
    if (t == 1023) rowptr[n] = sh[1023];

    for (int i = t; i < G_GRAPHS * OUT_DIM; i += 1024) feat[i] = 0.f;
    for (int i = t; i < 3 * 2 * HD_MAX; i += 1024) stat[i] = 0.f;
    if (t <= G_GRAPHS) {
        if (t == G_GRAPHS) start[G_GRAPHS] = n;
        else {
            int lo = 0, hi = n;
            while (lo < hi) {
                int mid = (lo + hi) >> 1;
                if (batch[mid] < t) lo = mid + 1; else hi = mid;
            }
            start[t] = lo;
        }
    }
}

__global__ void k_fill(const int* __restrict__ ei, int E, int ET,
                       int* __restrict__ cursor, int* __restrict__ csrc) {
    int e = blockIdx.x * blockDim.x + threadIdx.x;
    if (e >= ET) return;
    int s, d;
    if (e < E) { s = ei[e]; d = ei[E + e]; }
    else { s = e - E; d = e - E; }
    int pos = atomicAdd(&cursor[d], 1);
    csrc[pos] = s;
}

// ---------------- fp16 helpers ----------------
__device__ __forceinline__ uint32_t pack_h16(float x0, float x1) {
    __half2 h = __floats2half2_rn(x0, x1);
    return *(uint32_t*)&h;
}
__device__ __forceinline__ void mma_fp16(float* c, const uint32_t* a, uint32_t b0, uint32_t b1) {
    asm volatile(
        "mma.sync.aligned.m16n8k16.row.col.f32.f16.f16.f32 "
        "{%0,%1,%2,%3}, {%4,%5,%6,%7}, {%8,%9}, {%0,%1,%2,%3};"
        : "+f"(c[0]), "+f"(c[1]), "+f"(c[2]), "+f"(c[3])
        : "r"(a[0]), "r"(a[1]), "r"(a[2]), "r"(a[3]), "r"(b0), "r"(b1));
}

// ---------------- Tensor-core GEMM: fp16, 128x64 tiles, KT=32 ----------------------
// AHALF: A operand stored fp16 (layer 1,2 activations); else fp32 (layer-0 input x).
#define APAD 136
#define BPAD 72
template <bool FUSE, bool AHALF>
__global__ __launch_bounds__(256, 3) void k_gemm_tc(const void* __restrict__ Avoid,
                                                    const float* __restrict__ B,
                                                    __half* __restrict__ C,
                                                    int M, int K, int Nd, int nNodes,
                                                    const float* __restrict__ bnsum,
                                                    const float* __restrict__ bnsq,
                                                    const float* __restrict__ gamma,
                                                    const float* __restrict__ beta,
                                                    const float* __restrict__ asrc,
                                                    const float* __restrict__ adst,
                                                    float* __restrict__ es,
                                                    float* __restrict__ ed) {
    __shared__ __align__(16) uint32_t Ah[2][16][APAD];
    __shared__ __align__(16) uint32_t Bh[2][16][BPAD];
    __shared__ float ssc[HD_MAX], ssh[HD_MAX];
    __shared__ float sAs[64], sAd[64];
    __shared__ float sE[128][2][2];
    int t = threadIdx.x;
    int bm = blockIdx.x * 128, bn = blockIdx.y * 64;

    if (t < 64) { sAs[t] = asrc[bn + t]; sAd[t] = adst[bn + t]; }
    if (FUSE && t < K) {
        float mu = bnsum[t] / (float)nNodes;
        float var = bnsq[t] / (float)nNodes - mu * mu;
        float sc = gamma[t] * rsqrtf(var + EPS_BN);
        ssc[t] = sc;
        ssh[t] = beta[t] - mu * sc;
    }
    __syncthreads();

    int warp = t >> 5, lane = t & 31;
    int wm = (warp >> 1) * 32, wcol = warp & 1, wn = wcol * 32;
    int gid = lane >> 2, tig = lane & 3;

    int ar = t >> 1, akb = (t & 1) * 16;
    bool avalid = (bm + ar) < M;
    const float*  Af = (const float*)Avoid + (size_t)(bm + ar) * K + akb;
    const __half* Ag = (const __half*)Avoid + (size_t)(bm + ar) * K + akb;
    const float* Bp = B + (size_t)(warp * 4) * Nd + bn + lane * 2;

    float acc[2][4][4];
#pragma unroll
    for (int mt = 0; mt < 2; mt++)
#pragma unroll
        for (int nt = 0; nt < 4; nt++)
#pragma unroll
            for (int c = 0; c < 4; c++) acc[mt][nt][c] = 0.f;

    float4 a0, a1, a2, a3;
    uint4 au0, au1;
    float2 b0, b1, b2, b3;

    auto gload = [&](int k0) {
        if (AHALF) {
            if (avalid) {
                au0 = *(const uint4*)(Ag + k0);
                au1 = *(const uint4*)(Ag + k0 + 8);
            } else {
                au0 = make_uint4(0, 0, 0, 0); au1 = au0;
            }
        } else {
            if (avalid) {
                a0 = *(const float4*)(Af + k0);
                a1 = *(const float4*)(Af + k0 + 4);
                a2 = *(const float4*)(Af + k0 + 8);
                a3 = *(const float4*)(Af + k0 + 12);
            } else {
                a0 = make_float4(0, 0, 0, 0); a1 = a0; a2 = a0; a3 = a0;
            }
        }
        b0 = *(const float2*)(Bp + (size_t)k0 * Nd);
        b1 = *(const float2*)(Bp + (size_t)(k0 + 1) * Nd);
        b2 = *(const float2*)(Bp + (size_t)(k0 + 2) * Nd);
        b3 = *(const float2*)(Bp + (size_t)(k0 + 3) * Nd);
    };

    auto stage = [&](int buf, int k0) {
        float v[16];
        if (AHALF) {
            const __half2* h0 = (const __half2*)&au0;
            const __half2* h1 = (const __half2*)&au1;
#pragma unroll
            for (int j = 0; j < 4; j++) {
                float2 f = __half22float2(h0[j]);
                v[2 * j] = f.x; v[2 * j + 1] = f.y;
            }
#pragma unroll
            for (int j = 0; j < 4; j++) {
                float2 f = __half22float2(h1[j]);
                v[8 + 2 * j] = f.x; v[9 + 2 * j] = f.y;
            }
        } else {
            v[0] = a0.x; v[1] = a0.y; v[2] = a0.z; v[3] = a0.w;
            v[4] = a1.x; v[5] = a1.y; v[6] = a1.z; v[7] = a1.w;
            v[8] = a2.x; v[9] = a2.y; v[10] = a2.z; v[11] = a2.w;
            v[12] = a3.x; v[13] = a3.y; v[14] = a3.z; v[15] = a3.w;
        }
        if (FUSE) {
#pragma unroll
            for (int j = 0; j < 16; j++)
                v[j] = fmaxf(v[j] * ssc[k0 + akb + j] + ssh[k0 + akb + j], 0.f);
        }
#pragma unroll
        for (int j2 = 0; j2 < 8; j2++)
            Ah[buf][(akb >> 1) + j2][ar] = pack_h16(v[2 * j2], v[2 * j2 + 1]);
        Bh[buf][warp * 2][lane * 2]         = pack_h16(b0.x, b1.x);
        Bh[buf][warp * 2][lane * 2 + 1]     = pack_h16(b0.y, b1.y);
        Bh[buf][warp * 2 + 1][lane * 2]     = pack_h16(b2.x, b3.x);
        Bh[buf][warp * 2 + 1][lane * 2 + 1] = pack_h16(b2.y, b3.y);
    };

    gload(0);
    stage(0, 0);
    __syncthreads();

    int nk = K >> 5;
    for (int kt = 0; kt < nk; kt++) {
        int buf = kt & 1;
        if (kt + 1 < nk) gload((kt + 1) << 5);

#pragma unroll
        for (int ks = 0; ks < 2; ks++) {
            uint32_t fbh[4][2];
#pragma unroll
            for (int nt = 0; nt < 4; nt++) {
                int c0 = wn + nt * 8 + gid;
                fbh[nt][0] = Bh[buf][ks * 8 + tig][c0];
                fbh[nt][1] = Bh[buf][ks * 8 + tig + 4][c0];
            }
#pragma unroll
            for (int mt = 0; mt < 2; mt++) {
                int r0i = wm + mt * 16 + gid;
                uint32_t ah[4];
                ah[0] = Ah[buf][ks * 8 + tig][r0i];
                ah[1] = Ah[buf][ks * 8 + tig][r0i + 8];
                ah[2] = Ah[buf][ks * 8 + tig + 4][r0i];
                ah[3] = Ah[buf][ks * 8 + tig + 4][r0i + 8];
#pragma unroll
                for (int nt = 0; nt < 4; nt++)
                    mma_fp16(acc[mt][nt], ah, fbh[nt][0], fbh[nt][1]);
            }
        }

        if (kt + 1 < nk) stage(buf ^ 1, (kt + 1) << 5);
        __syncthreads();
    }

    // ---- epilogue: store C (fp16) + attention-score partials ----
    uint32_t* Cb = (uint32_t*)C;
#pragma unroll
    for (int mt = 0; mt < 2; mt++) {
        int r0i = bm + wm + mt * 16 + gid;
        int r1i = r0i + 8;
#pragma unroll
        for (int nt = 0; nt < 4; nt++) {
            int cc = bn + wn + nt * 8 + tig * 2;
            if (r0i < M) Cb[((size_t)r0i * Nd + cc) >> 1] =
                pack_h16(acc[mt][nt][0], acc[mt][nt][1]);
            if (r1i < M) Cb[((size_t)r1i * Nd + cc) >> 1] =
                pack_h16(acc[mt][nt][2], acc[mt][nt][3]);
        }
#pragma unroll
        for (int half = 0; half < 2; half++) {
            float pes = 0.f, ped = 0.f;
#pragma unroll
            for (int nt = 0; nt < 4; nt++) {
#pragma unroll
                for (int j = 0; j < 2; j++) {
                    int cl = wn + nt * 8 + tig * 2 + j;
                    float v = acc[mt][nt][half * 2 + j];
                    pes += v * sAs[cl];
                    ped += v * sAd[cl];
                }
            }
            pes += __shfl_xor_sync(0xffffffffu, pes, 1);
            pes += __shfl_xor_sync(0xffffffffu, pes, 2);
            ped += __shfl_xor_sync(0xffffffffu, ped, 1);
            ped += __shfl_xor_sync(0xffffffffu, ped, 2);
            if (tig == 0) {
                int r = wm + mt * 16 + gid + half * 8;
                sE[r][wcol][0] = pes;
                sE[r][wcol][1] = ped;
            }
        }
    }
    __syncthreads();
    if (t < 128) {
        int row = bm + t;
        if (row < M) {
            es[row * 4 + blockIdx.y] = sE[t][0][0] + sE[t][1][0];
            ed[row * 4 + blockIdx.y] = sE[t][0][1] + sE[t][1][1];
        }
    }
}

// ---------------- single-pass softmax + aggregation (fp16 gather/store) + BN stats --
template <int H, int D>
__global__ __launch_bounds__(256) void k_agg_fused(
        const __half* __restrict__ h, const float* __restrict__ es,
        const float* __restrict__ ed, const int* __restrict__ rowptr,
        const int* __restrict__ csrc, const float* __restrict__ bias,
        __half* __restrict__ outp, float* __restrict__ bnsum,
        float* __restrict__ bnsq, int n) {
    constexpr int HD = H * D, PL = HD / 32, NV = PL / 4;
    __shared__ float sm8[8][HD];
    int t = threadIdx.x;
    int node = (blockIdx.x * 256 + t) >> 5;
    int lane = t & 31;
    int warp = t >> 5;
    const int hme = (lane * PL) / D;

    float4 res[NV];
#pragma unroll
    for (int q = 0; q < NV; q++) res[q] = make_float4(0.f, 0.f, 0.f, 0.f);

    if (node < n) {
        float edme;
        if (H == 1) edme = ed[node * 4] + ed[node * 4 + 1];
        else        edme = ed[node * 4 + hme];
        int p0 = rowptr[node], p1 = rowptr[node + 1];
        float4 acc[NV];
#pragma unroll
        for (int q = 0; q < NV; q++) acc[q] = make_float4(0.f, 0.f, 0.f, 0.f);
        float z = 0.f;
#pragma unroll 2
        for (int p = p0; p < p1; p++) {
            int s = csrc[p];
            float e;
            if (H == 1) {
                float2 e2 = *(const float2*)&es[s * 4];
                e = e2.x + e2.y + edme;
            } else {
                e = es[s * 4 + hme] + edme;
            }
            e = (e > 0.f) ? e : NEG_SLOPE * e;
            float w = __expf(e);
            z += w;
            const __half* hs = h + (size_t)s * HD + lane * PL;
            uint32_t u[PL / 2];
            if (PL == 8) *(uint4*)u = *(const uint4*)hs;
            else         *(uint2*)u = *(const uint2*)hs;
#pragma unroll
            for (int q = 0; q < NV; q++) {
                float2 f0 = __half22float2(*(__half2*)&u[q * 2]);
                float2 f1 = __half22float2(*(__half2*)&u[q * 2 + 1]);
                acc[q].x += f0.x * w; acc[q].y += f0.y * w;
                acc[q].z += f1.x * w; acc[q].w += f1.y * w;
            }
        }
        float iz = 1.f / z;
        const float4* bb = (const float4*)(bias + lane * PL);
        uint32_t* op = (uint32_t*)(outp + (size_t)node * HD + lane * PL);
#pragma unroll
        for (int q = 0; q < NV; q++) {
            float4 b = bb[q];
            res[q] = make_float4(acc[q].x * iz + b.x, acc[q].y * iz + b.y,
                                 acc[q].z * iz + b.z, acc[q].w * iz + b.w);
            op[q * 2]     = pack_h16(res[q].x, res[q].y);
            op[q * 2 + 1] = pack_h16(res[q].z, res[q].w);
        }
    }

    // BN stats from fp32 registers: stage rows, channel reduce, 2 global atomics/ch
#pragma unroll
    for (int q = 0; q < NV; q++)
        *(float4*)&sm8[warp][lane * PL + q * 4] = res[q];
    __syncthreads();
    if (t < HD) {
        float s = 0.f, q2 = 0.f;
#pragma unroll
        for (int w = 0; w < 8; w++) {
            float v = sm8[w][t];
            s += v;
            q2 += v * v;
        }
        atomicAdd(&bnsum[t], s);
        atomicAdd(&bnsq[t], q2);
    }
}

// ---------------- pooling (fp16 o; BN scale/shift from stats) ----------------------
__global__ void k_pool(const __half* __restrict__ o, const int* __restrict__ start,
                       const float* __restrict__ bnsum, const float* __restrict__ bnsq,
                       const float* __restrict__ gamma, const float* __restrict__ beta,
                       int n, float* __restrict__ feat) {
    __shared__ float sm[4][OUT_DIM];
    __shared__ float ssc[OUT_DIM], ssh[OUT_DIM];
    int c = threadIdx.x & 127;
    int rgrp = threadIdx.x >> 7;
    if (threadIdx.x < OUT_DIM) {
        float mu = bnsum[c] / (float)n;
        float var = bnsq[c] / (float)n - mu * mu;
        float sc2 = gamma[c] * rsqrtf(var + EPS_BN);
        ssc[c] = sc2;
        ssh[c] = beta[c] - mu * sc2;
    }
    __syncthreads();
    int g = blockIdx.x;
    int part = blockIdx.y;
    int s0 = start[g], s1 = start[g + 1];
    int len = s1 - s0;
    int chunk = (len + 3) >> 2;
    int r0 = s0 + part * chunk;
    int r1 = min(s1, r0 + chunk);
    float sc = ssc[c], sh = ssh[c];
    float sum = 0.f;
    for (int r = r0 + rgrp; r < r1; r += 4) {
        float v = __half2float(o[(size_t)r * OUT_DIM + c]);
        sum += fmaxf(v * sc + sh, 0.f);
    }
    sm[rgrp][c] = sum;
    __syncthreads();
    if (threadIdx.x < OUT_DIM) {
        float s = sm[0][c] + sm[1][c] + sm[2][c] + sm[3][c];
        atomicAdd(&feat[g * OUT_DIM + c], s);
    }
}

// ---------------- heads ----------------
__global__ void k_heads(const float* __restrict__ featsum, const int* __restrict__ start,
                        const float* __restrict__ clfW, const float* __restrict__ clfb,
                        const float* __restrict__ dW1, const float* __restrict__ db1,
                        const float* __restrict__ dW2, const float* __restrict__ db2,
                        float* __restrict__ out) {
    __shared__ float f[OUT_DIM];
    __shared__ float dh[64];
    int g = blockIdx.x, t = threadIdx.x;
    float c = (float)max(start[g + 1] - start[g], 1);
    f[t] = featsum[g * OUT_DIM + t] / c;
    out[G_GRAPHS * NCLS_D + G_GRAPHS * 2 + g * OUT_DIM + t] = f[t];
    __syncthreads();
    if (t < 64) {
        float s = db1[t];
        for (int k = 0; k < OUT_DIM; k++) s += f[k] * dW1[k * 64 + t];
        dh[t] = fmaxf(s, 0.f);
    }
    if (t < NCLS_D) {
        float s = clfb[t];
        for (int k = 0; k < OUT_DIM; k++) s += f[k] * clfW[k * NCLS_D + t];
        out[g * NCLS_D + t] = s;
    }
    __syncthreads();
    if (t < 2) {
        float s = db2[t];
        for (int k = 0; k < 64; k++) s += dh[k] * dW2[k * 2 + t];
        out[G_GRAPHS * NCLS_D + g * 2 + t] = s;
    }
}

// ---------------- launch ----------------
static inline int cdiv(int a, int b) { return (a + b - 1) / b; }

extern "C" void kernel_launch(void* const* d_in, const int* in_sizes, int n_in,
                              void* d_out, int out_size) {
    const float* x = (const float*)d_in[0];
    const int* ei = (const int*)d_in[1];
    const int* batch = (const int*)d_in[2];
    const float* W[3]   = {(const float*)d_in[3],  (const float*)d_in[9],  (const float*)d_in[15]};
    const float* Asr[3] = {(const float*)d_in[4],  (const float*)d_in[10], (const float*)d_in[16]};
    const float* Ads[3] = {(const float*)d_in[5],  (const float*)d_in[11], (const float*)d_in[17]};
    const float* Bi[3]  = {(const float*)d_in[6],  (const float*)d_in[12], (const float*)d_in[18]};
    const float* Ga[3]  = {(const float*)d_in[7],  (const float*)d_in[13], (const float*)d_in[19]};
    const float* Be[3]  = {(const float*)d_in[8],  (const float*)d_in[14], (const float*)d_in[20]};
    const float* clfW = (const float*)d_in[21];
    const float* clfb = (const float*)d_in[22];
    const float* dW1 = (const float*)d_in[23];
    const float* db1 = (const float*)d_in[24];
    const float* dW2 = (const float*)d_in[25];
    const float* db2 = (const float*)d_in[26];

    int N = in_sizes[0] / F_IN_D;
    int E = in_sizes[1] / 2;
    int ET = E + N;

    float *p_es, *p_ed, *p_stat, *p_feat;
    __half *p_h, *p_o;
    int *p_deg, *p_rowptr, *p_cursor, *p_csrc, *p_start;
    cudaGetSymbolAddress((void**)&p_h, g_h);
    cudaGetSymbolAddress((void**)&p_o, g_o);
    cudaGetSymbolAddress((void**)&p_es, g_es);
    cudaGetSymbolAddress((void**)&p_ed, g_ed);
    cudaGetSymbolAddress((void**)&p_deg, g_deg);
    cudaGetSymbolAddress((void**)&p_rowptr, g_rowptr);
    cudaGetSymbolAddress((void**)&p_cursor, g_cursor);
    cudaGetSymbolAddress((void**)&p_csrc, g_csrc);
    cudaGetSymbolAddress((void**)&p_stat, g_bnstat);
    cudaGetSymbolAddress((void**)&p_feat, g_feat);
    cudaGetSymbolAddress((void**)&p_start, g_start);

    const int Kd[3] = {F_IN_D, 256, 256};
    const int Hh[3] = {4, 4, 1};

    // GEMM layer0 at launch index 3 so the ncu window lands on it.
    k_zero_i<<<cdiv(N, 256), 256>>>(p_deg, N);
    k_deg<<<cdiv(ET, 256), 256>>>(ei, E, ET, p_deg);
    k_scan<<<1, 1024>>>(p_deg, p_rowptr, p_cursor, N, batch, p_start, p_feat, p_stat);
    {
        dim3 gg(cdiv(N, 128), 4);
        k_gemm_tc<false, false><<<gg, 256>>>(x, W[0], p_h, N, Kd[0], 256, N,
                                             nullptr, nullptr, nullptr, nullptr,
                                             Asr[0], Ads[0], p_es, p_ed);
    }
    k_fill<<<cdiv(ET, 256), 256>>>(ei, E, ET, p_cursor, p_csrc);

    for (int li = 0; li < 3; li++) {
        int HD = (li < 2) ? 256 : 128;
        float* bnsum = p_stat + li * 2 * HD_MAX;
        float* bnsq = bnsum + HD_MAX;
        if (li > 0) {
            float* psum = p_stat + (li - 1) * 2 * HD_MAX;
            float* psq = psum + HD_MAX;
            dim3 gg(cdiv(N, 128), HD / 64);
            k_gemm_tc<true, true><<<gg, 256>>>(p_o, W[li], p_h, N, Kd[li], HD, N,
                                               psum, psq, Ga[li - 1], Be[li - 1],
                                               Asr[li], Ads[li], p_es, p_ed);
        }

        int aggBlocks = cdiv(N * 32, 256);
        if (Hh[li] == 4) {
            k_agg_fused<4, 64><<<aggBlocks, 256>>>(p_h, p_es, p_ed, p_rowptr, p_csrc,
                                                   Bi[li], p_o, bnsum, bnsq, N);
        } else {
            k_agg_fused<1, 128><<<aggBlocks, 256>>>(p_h, p_es, p_ed, p_rowptr, p_csrc,
                                                    Bi[li], p_o, bnsum, bnsq, N);
        }
    }

    // --- pooling + heads (layer-2 BN folded into pool) ---
    {
        float* bnsum2 = p_stat + 2 * 2 * HD_MAX;
        float* bnsq2 = bnsum2 + HD_MAX;
        dim3 pg(G_GRAPHS, 4);
        k_pool<<<pg, 512>>>(p_o, p_start, bnsum2, bnsq2, Ga[2], Be[2], N, p_feat);
    }
    k_heads<<<G_GRAPHS, 128>>>(p_feat, p_start, clfW, clfb, dW1, db1, dW2, db2,
                               (float*)d_out);
}